// round 11
// baseline (speedup 1.0000x reference)
#include <cuda_runtime.h>
#include <cuda_fp16.h>
#include <cstdint>
#include <math.h>

// Problem dims
#define B_    16
#define CIN   512
#define COUT  512
#define H_    64
#define W_    64
#define HW    4096
#define SDIM  32
#define OH    128
#define OW    128
#define EPS   1e-8f

// Scratch
__device__ float    g_s[B_ * CIN];
__device__ float    g_demod[B_ * COUT];
__device__ uint32_t g_wh[(size_t)B_ * COUT * CIN / 2];   // fp16 A-fragment-ordered weights (8 MB)
__device__ uint4    g_xf[(size_t)B_ * 16 * 512 * 32];    // fp16 B-fragment-ordered x (67 MB)
__device__ __half   g_yh[(size_t)B_ * COUT * HW];        // conv output, fp16 (67 MB)

// ---------------------------------------------------------------------------
// Kernel A1: s[b,cin], demod[b,cout]. grid (8, 16), 256 threads.
// ---------------------------------------------------------------------------
__global__ __launch_bounds__(256) void mod_demod_kernel(
    const float* __restrict__ style,
    const float* __restrict__ conv_w,
    const float* __restrict__ mod_w,
    const float* __restrict__ mod_b)
{
    int og = blockIdx.x;
    int b  = blockIdx.y;
    int tid = threadIdx.x;
    __shared__ float s_sh[CIN];

    const float* st = style + b * SDIM;
#pragma unroll
    for (int rep = 0; rep < 2; rep++) {
        int i = tid + rep * 256;
        float acc = mod_b[i];
        const float* mw = mod_w + i * SDIM;
#pragma unroll
        for (int k = 0; k < SDIM; k++) acc += st[k] * mw[k];
        s_sh[i] = acc;
        if (og == 0) g_s[b * CIN + i] = acc;
    }
    __syncthreads();

    int wid = tid >> 5, lane = tid & 31;
#pragma unroll
    for (int cc = 0; cc < 8; cc++) {
        int o = og * 64 + wid * 8 + cc;
        const float* cw = conv_w + (size_t)o * CIN;
        float sum = 0.f;
#pragma unroll
        for (int it = 0; it < 4; it++) {
            int k4 = lane + it * 32;
            float4 v = __ldg((const float4*)cw + k4);
            int k = k4 * 4;
            float t0 = v.x * s_sh[k], t1 = v.y * s_sh[k + 1];
            float t2 = v.z * s_sh[k + 2], t3 = v.w * s_sh[k + 3];
            sum += t0 * t0 + t1 * t1 + t2 * t2 + t3 * t3;
        }
#pragma unroll
        for (int off = 16; off; off >>= 1)
            sum += __shfl_xor_sync(0xFFFFFFFFu, sum, off);
        if (lane == 0) g_demod[b * COUT + o] = rsqrtf(sum + EPS);
    }
}

// ---------------------------------------------------------------------------
// Kernel A2: fp16 weights in m16n8k16 A-fragment order.
// ---------------------------------------------------------------------------
__global__ __launch_bounds__(256) void wfrag_kernel(
    const float* __restrict__ conv_w)
{
    int c  = blockIdx.x;
    int ot = blockIdx.y;
    int b  = blockIdx.z;
    int tid = threadIdx.x;
    int lane = tid & 31, fg = tid >> 5;
    int gid = lane >> 2, tg = lane & 3;

    uint32_t* cb = g_wh + ((size_t)((b * 4 + ot) * 16 + c)) * 2048;

#pragma unroll
    for (int rep = 0; rep < 2; rep++) {
        int fgrp = fg + rep * 8;
        int g  = fgrp >> 3;
        int s  = (fgrp >> 2) & 1;
        int mt = fgrp & 3;
        int o0 = ot * 128 + g * 64 + mt * 16 + gid;
        int o1 = o0 + 8;
        int k0 = c * 32 + s * 16 + tg * 2;

        float d0 = __ldg(g_demod + b * COUT + o0);
        float d1 = __ldg(g_demod + b * COUT + o1);
        float s00 = __ldg(g_s + b * CIN + k0);
        float s01 = __ldg(g_s + b * CIN + k0 + 1);
        float s08 = __ldg(g_s + b * CIN + k0 + 8);
        float s09 = __ldg(g_s + b * CIN + k0 + 9);

        float2 w0a = __ldg((const float2*)(conv_w + (size_t)o0 * CIN + k0));
        float2 w0b = __ldg((const float2*)(conv_w + (size_t)o0 * CIN + k0 + 8));
        float2 w1a = __ldg((const float2*)(conv_w + (size_t)o1 * CIN + k0));
        float2 w1b = __ldg((const float2*)(conv_w + (size_t)o1 * CIN + k0 + 8));

        __half2 h0 = __floats2half2_rn(w0a.x * s00 * d0, w0a.y * s01 * d0);
        __half2 h1 = __floats2half2_rn(w1a.x * s00 * d1, w1a.y * s01 * d1);
        __half2 h2 = __floats2half2_rn(w0b.x * s08 * d0, w0b.y * s09 * d0);
        __half2 h3 = __floats2half2_rn(w1b.x * s08 * d1, w1b.y * s09 * d1);

        uint4 u;
        u.x = *(uint32_t*)&h0; u.y = *(uint32_t*)&h1;
        u.z = *(uint32_t*)&h2; u.w = *(uint32_t*)&h3;
        *(uint4*)(cb + fgrp * 128 + lane * 4) = u;
    }
}

// ---------------------------------------------------------------------------
// Kernel A3: x -> B-fragment order, smem-staged (coalesced reads).
// Block = (seg, c, b): rows c*32..+31, pixels seg*512..+511.
// Phase 1: row-pair half2 tile st[16][520] via float4 reads + STS.128.
// Phase 2: fragment gather (conflict-free via pad 8) + coalesced uint4 writes.
// ---------------------------------------------------------------------------
__global__ __launch_bounds__(256) void xcvt_kernel(const float* __restrict__ x)
{
    __shared__ __half2 st[16][520];
    int seg = blockIdx.x;     // 0..7
    int c   = blockIdx.y;     // 0..15
    int b   = blockIdx.z;     // 0..15
    int tid = threadIdx.x;

    // Phase 1: rp = tid>>4 (0..15), px base (tid&15)*4, 8 iters of stride 64.
    int rp = tid >> 4;
    int pxb = (tid & 15) * 4;
    const float* r0p = x + ((size_t)b * CIN + c * 32 + 2 * rp) * HW + seg * 512;
    const float* r1p = r0p + HW;
#pragma unroll
    for (int it = 0; it < 8; it++) {
        int px = pxb + it * 64;
        float4 f0 = __ldg((const float4*)(r0p + px));
        float4 f1 = __ldg((const float4*)(r1p + px));
        __half2 h0 = __floats2half2_rn(f0.x, f1.x);
        __half2 h1 = __floats2half2_rn(f0.y, f1.y);
        __half2 h2 = __floats2half2_rn(f0.z, f1.z);
        __half2 h3 = __floats2half2_rn(f0.w, f1.w);
        uint4 u;
        u.x = *(uint32_t*)&h0; u.y = *(uint32_t*)&h1;
        u.z = *(uint32_t*)&h2; u.w = *(uint32_t*)&h3;
        *(uint4*)&st[rp][px] = u;
    }
    __syncthreads();

    // Phase 2: lane = tid&31, warp w = tid>>5; n8_local = it*8 + w.
    int lane = tid & 31;
    int w = tid >> 5;
    int gid = lane >> 2, tg = lane & 3;
    uint4* dst = g_xf + ((size_t)(b * 16 + c) * 512 + seg * 64) * 32 + lane;
#pragma unroll
    for (int it = 0; it < 8; it++) {
        int n8l = it * 8 + w;
        int p = n8l * 8 + gid;
        uint4 u;
        u.x = *(uint32_t*)&st[tg +  0][p];
        u.y = *(uint32_t*)&st[tg +  4][p];
        u.z = *(uint32_t*)&st[tg +  8][p];
        u.w = *(uint32_t*)&st[tg + 12][p];
        dst[(size_t)n8l * 32] = u;
    }
}

// ---------------------------------------------------------------------------
// Kernel B: batched GEMM, mma.sync.m16n8k16.f16.
// 5-stage cp.async, one sync per chunk: wait 3 -> sync -> bv LDS -> issue -> mma.
// ---------------------------------------------------------------------------
#define A_U32 2048
#define B_U32 2048
#define STAGE_U32 (A_U32 + B_U32)
#define NSTAGE 5
#define SM_GEMM_BYTES (NSTAGE * STAGE_U32 * 4)   // 81920

__device__ __forceinline__ uint32_t smem_u32(const void* p) {
    uint32_t a;
    asm("{ .reg .u64 t; cvta.to.shared.u64 t, %1; cvt.u32.u64 %0, t; }" : "=r"(a) : "l"(p));
    return a;
}

__global__ __launch_bounds__(256, 2) void gemm_mma(void)
{
    extern __shared__ uint32_t smu[];

    int tid = threadIdx.x;
    int wid = tid >> 5, lane = tid & 31;
    int gid = lane >> 2, tg = lane & 3;
    int b = blockIdx.z, oTile = blockIdx.y * 128, pTile = blockIdx.x * 128;
    int g = wid >> 2, wn = (wid & 3) * 32, wnb = (wid & 3) * 4;

    const uint32_t* aglob = g_wh + ((size_t)((b * 4 + blockIdx.y) * 16)) * 2048;
    const uint4*    bglob = g_xf + (size_t)b * 262144 + (size_t)(pTile >> 3) * 32;

    uint32_t sm_u = smem_u32(smu);

    auto issue = [&](int ch) {
        int buf = ch % NSTAGE;
        uint32_t stage = sm_u + buf * STAGE_U32 * 4;
        const uint32_t* as_ = aglob + ch * 2048 + tid * 8;
        uint32_t ad = stage + tid * 32;
        asm volatile("cp.async.cg.shared.global [%0], [%1], 16;" :: "r"(ad),      "l"(as_)     : "memory");
        asm volatile("cp.async.cg.shared.global [%0], [%1], 16;" :: "r"(ad + 16), "l"(as_ + 4) : "memory");
        const uint4* bs_ = bglob + (size_t)ch * 16384 + tid * 2;
        uint32_t bd = stage + A_U32 * 4 + tid * 32;
        asm volatile("cp.async.cg.shared.global [%0], [%1], 16;" :: "r"(bd),      "l"(bs_)     : "memory");
        asm volatile("cp.async.cg.shared.global [%0], [%1], 16;" :: "r"(bd + 16), "l"(bs_ + 1) : "memory");
        asm volatile("cp.async.commit_group;" ::: "memory");
    };

    float c[4][4][4];
#pragma unroll
    for (int mt = 0; mt < 4; mt++)
#pragma unroll
        for (int nt = 0; nt < 4; nt++)
#pragma unroll
            for (int q = 0; q < 4; q++) c[mt][nt][q] = 0.f;

    issue(0); issue(1); issue(2); issue(3);

    const int NCH = CIN / 32;   // 16
    for (int ch = 0; ch < NCH; ch++) {
        if (ch + 3 < NCH) {
            asm volatile("cp.async.wait_group 3;" ::: "memory");
        } else if (ch + 2 < NCH) {
            asm volatile("cp.async.wait_group 2;" ::: "memory");
        } else if (ch + 1 < NCH) {
            asm volatile("cp.async.wait_group 1;" ::: "memory");
        } else {
            asm volatile("cp.async.wait_group 0;" ::: "memory");
        }
        __syncthreads();

        int buf = ch % NSTAGE;
        const uint32_t* Ab = smu + buf * STAGE_U32 + g * 1024;
        const uint4*    Bb = (const uint4*)(smu + buf * STAGE_U32 + A_U32);

        // B fragments first: LDS latency overlaps the cp.async issue below.
        uint4 bv[4];
#pragma unroll
        for (int nt = 0; nt < 4; nt++)
            bv[nt] = Bb[(wnb + nt) * 32 + lane];

        if (ch + 4 < NCH) issue(ch + 4);

#pragma unroll
        for (int s = 0; s < 2; s++) {
            uint32_t af[4][4];
#pragma unroll
            for (int mt = 0; mt < 4; mt++) {
                uint4 av = *(const uint4*)(Ab + (s * 4 + mt) * 128 + lane * 4);
                af[mt][0] = av.x; af[mt][1] = av.y; af[mt][2] = av.z; af[mt][3] = av.w;
            }
#pragma unroll
            for (int mt = 0; mt < 4; mt++)
#pragma unroll
                for (int nt = 0; nt < 4; nt++) {
                    uint32_t b0 = s ? bv[nt].z : bv[nt].x;
                    uint32_t b1 = s ? bv[nt].w : bv[nt].y;
                    asm volatile(
                        "mma.sync.aligned.m16n8k16.row.col.f32.f16.f16.f32 "
                        "{%0,%1,%2,%3}, {%4,%5,%6,%7}, {%8,%9}, {%0,%1,%2,%3};"
                        : "+f"(c[mt][nt][0]), "+f"(c[mt][nt][1]),
                          "+f"(c[mt][nt][2]), "+f"(c[mt][nt][3])
                        : "r"(af[mt][0]), "r"(af[mt][1]), "r"(af[mt][2]), "r"(af[mt][3]),
                          "r"(b0), "r"(b1));
                }
        }
    }

    // Epilogue: fp16 stores.
    __half* yb = g_yh + (size_t)b * COUT * HW;
#pragma unroll
    for (int mt = 0; mt < 4; mt++) {
        int r0 = oTile + g * 64 + mt * 16 + gid;
        int r1 = r0 + 8;
#pragma unroll
        for (int nt = 0; nt < 4; nt++) {
            int col = pTile + wn + nt * 8 + tg * 2;
            __half2 h0 = __floats2half2_rn(c[mt][nt][0], c[mt][nt][1]);
            __half2 h1 = __floats2half2_rn(c[mt][nt][2], c[mt][nt][3]);
            *(__half2*)(yb + (size_t)r0 * HW + col) = h0;
            *(__half2*)(yb + (size_t)r1 * HW + col) = h1;
        }
    }
}

// ---------------------------------------------------------------------------
// Kernel C: bilinear x2 upsample from fp16 y, smem-tiled, fp32 out.
// ---------------------------------------------------------------------------
__global__ __launch_bounds__(256) void upsample_kernel(float* __restrict__ out)
{
    __shared__ float ssm[64 * 68];
    unsigned c = blockIdx.x & 511u;
    unsigned b = blockIdx.x >> 9;
    int tid = threadIdx.x;
    int wid = tid >> 5, lane = tid & 31;

    const uint4* src = (const uint4*)(g_yh + ((size_t)b * COUT + c) * HW);
#pragma unroll
    for (int j = 0; j < 2; j++) {
        int idx = tid + j * 256;
        int row = idx >> 3, col8 = idx & 7;
        uint4 v = __ldg(src + idx);
        float* dst = ssm + row * 68 + col8 * 8;
        float2 f0 = __half22float2(*(__half2*)&v.x);
        float2 f1 = __half22float2(*(__half2*)&v.y);
        float2 f2 = __half22float2(*(__half2*)&v.z);
        float2 f3 = __half22float2(*(__half2*)&v.w);
        dst[0] = f0.x; dst[1] = f0.y; dst[2] = f1.x; dst[3] = f1.y;
        dst[4] = f2.x; dst[5] = f2.y; dst[6] = f3.x; dst[7] = f3.y;
    }
    __syncthreads();

    float* outp = out + ((size_t)b * COUT + c) * OH * OW;
#pragma unroll
    for (int i = 0; i < 16; i++) {
        int oy = i * 8 + wid;
        float fy  = oy * 0.5f - 0.25f;
        float y0f = floorf(fy);
        float wy  = fy - y0f;
        int iy0 = max(0, (int)y0f);
        int iy1 = min(63, (int)y0f + 1);
        const float* r0 = ssm + iy0 * 68;
        const float* r1 = ssm + iy1 * 68;
        float* orow = outp + (size_t)oy * OW;
#pragma unroll
        for (int seg = 0; seg < 2; seg++) {
            int xc = lane + seg * 32;
            int xm = max(0, xc - 1);
            int xp = min(63, xc + 1);
            float vm = r0[xm] + wy * (r1[xm] - r0[xm]);
            float vc = r0[xc] + wy * (r1[xc] - r0[xc]);
            float vp = r0[xp] + wy * (r1[xp] - r0[xp]);
            *(float2*)(orow + 2 * xc) =
                make_float2(0.25f * vm + 0.75f * vc, 0.75f * vc + 0.25f * vp);
        }
    }
}

// ---------------------------------------------------------------------------
extern "C" void kernel_launch(void* const* d_in, const int* in_sizes, int n_in,
                              void* d_out, int out_size)
{
    const float* x      = (const float*)d_in[0];
    const float* style  = (const float*)d_in[1];
    const float* conv_w = (const float*)d_in[2];
    const float* mod_w  = (const float*)d_in[3];
    const float* mod_b  = (const float*)d_in[4];
    float* out = (float*)d_out;

    static cudaStream_t s_aux = nullptr;
    static cudaEvent_t ev_fork = nullptr, ev_join = nullptr;
    if (!s_aux) {
        cudaFuncSetAttribute(gemm_mma, cudaFuncAttributeMaxDynamicSharedMemorySize, SM_GEMM_BYTES);
        cudaStreamCreateWithFlags(&s_aux, cudaStreamNonBlocking);
        cudaEventCreateWithFlags(&ev_fork, cudaEventDisableTiming);
        cudaEventCreateWithFlags(&ev_join, cudaEventDisableTiming);
    }

    // Fork: xcvt (independent) on aux stream, weight prep on main stream.
    cudaEventRecord(ev_fork, 0);
    cudaStreamWaitEvent(s_aux, ev_fork, 0);
    dim3 xgrid(8, 16, 16);
    xcvt_kernel<<<xgrid, 256, 0, s_aux>>>(x);
    cudaEventRecord(ev_join, s_aux);

    dim3 mgrid(8, 16);
    mod_demod_kernel<<<mgrid, 256>>>(style, conv_w, mod_w, mod_b);
    dim3 fgrid(16, 4, 16);
    wfrag_kernel<<<fgrid, 256>>>(conv_w);

    // Join: GEMM needs both weight fragments and x fragments.
    cudaStreamWaitEvent(0, ev_join, 0);

    dim3 ggrid(HW / 128, COUT / 128, B_);   // (32, 4, 16)
    gemm_mma<<<ggrid, 256, SM_GEMM_BYTES>>>();

    upsample_kernel<<<B_ * COUT, 256>>>(out);
}

// round 12
// speedup vs baseline: 1.0466x; 1.0466x over previous
#include <cuda_runtime.h>
#include <cuda_fp16.h>
#include <cstdint>
#include <math.h>

// Problem dims
#define B_    16
#define CIN   512
#define COUT  512
#define H_    64
#define W_    64
#define HW    4096
#define SDIM  32
#define OH    128
#define OW    128
#define EPS   1e-8f

// Scratch
__device__ float    g_s[B_ * CIN];
__device__ float    g_demod[B_ * COUT];
__device__ uint32_t g_wh[(size_t)B_ * COUT * CIN / 2];   // fp16 A-fragment-ordered weights (8 MB)
__device__ uint4    g_xf[(size_t)B_ * 16 * 512 * 32];    // fp16 B-fragment-ordered x (67 MB)
__device__ __half   g_yh[(size_t)B_ * COUT * HW];        // conv output, fp16 (67 MB)

// ---------------------------------------------------------------------------
// Kernel A1: s[b,cin], demod[b,cout]. grid (8, 16), 256 threads.
// ---------------------------------------------------------------------------
__global__ __launch_bounds__(256) void mod_demod_kernel(
    const float* __restrict__ style,
    const float* __restrict__ conv_w,
    const float* __restrict__ mod_w,
    const float* __restrict__ mod_b)
{
    int og = blockIdx.x;
    int b  = blockIdx.y;
    int tid = threadIdx.x;
    __shared__ float s_sh[CIN];

    const float* st = style + b * SDIM;
#pragma unroll
    for (int rep = 0; rep < 2; rep++) {
        int i = tid + rep * 256;
        float acc = mod_b[i];
        const float* mw = mod_w + i * SDIM;
#pragma unroll
        for (int k = 0; k < SDIM; k++) acc += st[k] * mw[k];
        s_sh[i] = acc;
        if (og == 0) g_s[b * CIN + i] = acc;
    }
    __syncthreads();

    int wid = tid >> 5, lane = tid & 31;
#pragma unroll
    for (int cc = 0; cc < 8; cc++) {
        int o = og * 64 + wid * 8 + cc;
        const float* cw = conv_w + (size_t)o * CIN;
        float sum = 0.f;
#pragma unroll
        for (int it = 0; it < 4; it++) {
            int k4 = lane + it * 32;
            float4 v = __ldg((const float4*)cw + k4);
            int k = k4 * 4;
            float t0 = v.x * s_sh[k], t1 = v.y * s_sh[k + 1];
            float t2 = v.z * s_sh[k + 2], t3 = v.w * s_sh[k + 3];
            sum += t0 * t0 + t1 * t1 + t2 * t2 + t3 * t3;
        }
#pragma unroll
        for (int off = 16; off; off >>= 1)
            sum += __shfl_xor_sync(0xFFFFFFFFu, sum, off);
        if (lane == 0) g_demod[b * COUT + o] = rsqrtf(sum + EPS);
    }
}

// ---------------------------------------------------------------------------
// Kernel A2: fp16 weights in m16n8k16 A-fragment order.
// ---------------------------------------------------------------------------
__global__ __launch_bounds__(256) void wfrag_kernel(
    const float* __restrict__ conv_w)
{
    int c  = blockIdx.x;
    int ot = blockIdx.y;
    int b  = blockIdx.z;
    int tid = threadIdx.x;
    int lane = tid & 31, fg = tid >> 5;
    int gid = lane >> 2, tg = lane & 3;

    uint32_t* cb = g_wh + ((size_t)((b * 4 + ot) * 16 + c)) * 2048;

#pragma unroll
    for (int rep = 0; rep < 2; rep++) {
        int fgrp = fg + rep * 8;
        int g  = fgrp >> 3;
        int s  = (fgrp >> 2) & 1;
        int mt = fgrp & 3;
        int o0 = ot * 128 + g * 64 + mt * 16 + gid;
        int o1 = o0 + 8;
        int k0 = c * 32 + s * 16 + tg * 2;

        float d0 = __ldg(g_demod + b * COUT + o0);
        float d1 = __ldg(g_demod + b * COUT + o1);
        float s00 = __ldg(g_s + b * CIN + k0);
        float s01 = __ldg(g_s + b * CIN + k0 + 1);
        float s08 = __ldg(g_s + b * CIN + k0 + 8);
        float s09 = __ldg(g_s + b * CIN + k0 + 9);

        float2 w0a = __ldg((const float2*)(conv_w + (size_t)o0 * CIN + k0));
        float2 w0b = __ldg((const float2*)(conv_w + (size_t)o0 * CIN + k0 + 8));
        float2 w1a = __ldg((const float2*)(conv_w + (size_t)o1 * CIN + k0));
        float2 w1b = __ldg((const float2*)(conv_w + (size_t)o1 * CIN + k0 + 8));

        __half2 h0 = __floats2half2_rn(w0a.x * s00 * d0, w0a.y * s01 * d0);
        __half2 h1 = __floats2half2_rn(w1a.x * s00 * d1, w1a.y * s01 * d1);
        __half2 h2 = __floats2half2_rn(w0b.x * s08 * d0, w0b.y * s09 * d0);
        __half2 h3 = __floats2half2_rn(w1b.x * s08 * d1, w1b.y * s09 * d1);

        uint4 u;
        u.x = *(uint32_t*)&h0; u.y = *(uint32_t*)&h1;
        u.z = *(uint32_t*)&h2; u.w = *(uint32_t*)&h3;
        *(uint4*)(cb + fgrp * 128 + lane * 4) = u;
    }
}

// ---------------------------------------------------------------------------
// Kernel A3: x -> B-fragment order, smem-staged (coalesced reads).
// ---------------------------------------------------------------------------
__global__ __launch_bounds__(256) void xcvt_kernel(const float* __restrict__ x)
{
    __shared__ __half2 st[16][520];
    int seg = blockIdx.x;     // 0..7
    int c   = blockIdx.y;     // 0..15
    int b   = blockIdx.z;     // 0..15
    int tid = threadIdx.x;

    int rp = tid >> 4;
    int pxb = (tid & 15) * 4;
    const float* r0p = x + ((size_t)b * CIN + c * 32 + 2 * rp) * HW + seg * 512;
    const float* r1p = r0p + HW;
#pragma unroll
    for (int it = 0; it < 8; it++) {
        int px = pxb + it * 64;
        float4 f0 = __ldg((const float4*)(r0p + px));
        float4 f1 = __ldg((const float4*)(r1p + px));
        __half2 h0 = __floats2half2_rn(f0.x, f1.x);
        __half2 h1 = __floats2half2_rn(f0.y, f1.y);
        __half2 h2 = __floats2half2_rn(f0.z, f1.z);
        __half2 h3 = __floats2half2_rn(f0.w, f1.w);
        uint4 u;
        u.x = *(uint32_t*)&h0; u.y = *(uint32_t*)&h1;
        u.z = *(uint32_t*)&h2; u.w = *(uint32_t*)&h3;
        *(uint4*)&st[rp][px] = u;
    }
    __syncthreads();

    int lane = tid & 31;
    int w = tid >> 5;
    int gid = lane >> 2, tg = lane & 3;
    uint4* dst = g_xf + ((size_t)(b * 16 + c) * 512 + seg * 64) * 32 + lane;
#pragma unroll
    for (int it = 0; it < 8; it++) {
        int n8l = it * 8 + w;
        int p = n8l * 8 + gid;
        uint4 u;
        u.x = *(uint32_t*)&st[tg +  0][p];
        u.y = *(uint32_t*)&st[tg +  4][p];
        u.z = *(uint32_t*)&st[tg +  8][p];
        u.w = *(uint32_t*)&st[tg + 12][p];
        dst[(size_t)n8l * 32] = u;
    }
}

// ---------------------------------------------------------------------------
// Kernel B: batched GEMM, mma.sync.m16n8k16.f16.
// 5-stage cp.async, one sync per chunk: wait 3 -> sync -> bv LDS -> issue -> mma.
// ---------------------------------------------------------------------------
#define A_U32 2048
#define B_U32 2048
#define STAGE_U32 (A_U32 + B_U32)
#define NSTAGE 5
#define SM_GEMM_BYTES (NSTAGE * STAGE_U32 * 4)   // 81920

__device__ __forceinline__ uint32_t smem_u32(const void* p) {
    uint32_t a;
    asm("{ .reg .u64 t; cvta.to.shared.u64 t, %1; cvt.u32.u64 %0, t; }" : "=r"(a) : "l"(p));
    return a;
}

__global__ __launch_bounds__(256, 2) void gemm_mma(void)
{
    extern __shared__ uint32_t smu[];

    int tid = threadIdx.x;
    int wid = tid >> 5, lane = tid & 31;
    int gid = lane >> 2, tg = lane & 3;
    int b = blockIdx.z, oTile = blockIdx.y * 128, pTile = blockIdx.x * 128;
    int g = wid >> 2, wn = (wid & 3) * 32, wnb = (wid & 3) * 4;

    const uint32_t* aglob = g_wh + ((size_t)((b * 4 + blockIdx.y) * 16)) * 2048;
    const uint4*    bglob = g_xf + (size_t)b * 262144 + (size_t)(pTile >> 3) * 32;

    uint32_t sm_u = smem_u32(smu);

    auto issue = [&](int ch) {
        int buf = ch % NSTAGE;
        uint32_t stage = sm_u + buf * STAGE_U32 * 4;
        const uint32_t* as_ = aglob + ch * 2048 + tid * 8;
        uint32_t ad = stage + tid * 32;
        asm volatile("cp.async.cg.shared.global [%0], [%1], 16;" :: "r"(ad),      "l"(as_)     : "memory");
        asm volatile("cp.async.cg.shared.global [%0], [%1], 16;" :: "r"(ad + 16), "l"(as_ + 4) : "memory");
        const uint4* bs_ = bglob + (size_t)ch * 16384 + tid * 2;
        uint32_t bd = stage + A_U32 * 4 + tid * 32;
        asm volatile("cp.async.cg.shared.global [%0], [%1], 16;" :: "r"(bd),      "l"(bs_)     : "memory");
        asm volatile("cp.async.cg.shared.global [%0], [%1], 16;" :: "r"(bd + 16), "l"(bs_ + 1) : "memory");
        asm volatile("cp.async.commit_group;" ::: "memory");
    };

    float c[4][4][4];
#pragma unroll
    for (int mt = 0; mt < 4; mt++)
#pragma unroll
        for (int nt = 0; nt < 4; nt++)
#pragma unroll
            for (int q = 0; q < 4; q++) c[mt][nt][q] = 0.f;

    issue(0); issue(1); issue(2); issue(3);

    const int NCH = CIN / 32;   // 16
    for (int ch = 0; ch < NCH; ch++) {
        if (ch + 3 < NCH) {
            asm volatile("cp.async.wait_group 3;" ::: "memory");
        } else if (ch + 2 < NCH) {
            asm volatile("cp.async.wait_group 2;" ::: "memory");
        } else if (ch + 1 < NCH) {
            asm volatile("cp.async.wait_group 1;" ::: "memory");
        } else {
            asm volatile("cp.async.wait_group 0;" ::: "memory");
        }
        __syncthreads();

        int buf = ch % NSTAGE;
        const uint32_t* Ab = smu + buf * STAGE_U32 + g * 1024;
        const uint4*    Bb = (const uint4*)(smu + buf * STAGE_U32 + A_U32);

        // B fragments first: LDS latency overlaps the cp.async issue below.
        uint4 bv[4];
#pragma unroll
        for (int nt = 0; nt < 4; nt++)
            bv[nt] = Bb[(wnb + nt) * 32 + lane];

        if (ch + 4 < NCH) issue(ch + 4);

#pragma unroll
        for (int s = 0; s < 2; s++) {
            uint32_t af[4][4];
#pragma unroll
            for (int mt = 0; mt < 4; mt++) {
                uint4 av = *(const uint4*)(Ab + (s * 4 + mt) * 128 + lane * 4);
                af[mt][0] = av.x; af[mt][1] = av.y; af[mt][2] = av.z; af[mt][3] = av.w;
            }
#pragma unroll
            for (int mt = 0; mt < 4; mt++)
#pragma unroll
                for (int nt = 0; nt < 4; nt++) {
                    uint32_t b0 = s ? bv[nt].z : bv[nt].x;
                    uint32_t b1 = s ? bv[nt].w : bv[nt].y;
                    asm volatile(
                        "mma.sync.aligned.m16n8k16.row.col.f32.f16.f16.f32 "
                        "{%0,%1,%2,%3}, {%4,%5,%6,%7}, {%8,%9}, {%0,%1,%2,%3};"
                        : "+f"(c[mt][nt][0]), "+f"(c[mt][nt][1]),
                          "+f"(c[mt][nt][2]), "+f"(c[mt][nt][3])
                        : "r"(af[mt][0]), "r"(af[mt][1]), "r"(af[mt][2]), "r"(af[mt][3]),
                          "r"(b0), "r"(b1));
                }
        }
    }

    // Epilogue: fp16 stores.
    __half* yb = g_yh + (size_t)b * COUT * HW;
#pragma unroll
    for (int mt = 0; mt < 4; mt++) {
        int r0 = oTile + g * 64 + mt * 16 + gid;
        int r1 = r0 + 8;
#pragma unroll
        for (int nt = 0; nt < 4; nt++) {
            int col = pTile + wn + nt * 8 + tg * 2;
            __half2 h0 = __floats2half2_rn(c[mt][nt][0], c[mt][nt][1]);
            __half2 h1 = __floats2half2_rn(c[mt][nt][2], c[mt][nt][3]);
            *(__half2*)(yb + (size_t)r0 * HW + col) = h0;
            *(__half2*)(yb + (size_t)r1 * HW + col) = h1;
        }
    }
}

// ---------------------------------------------------------------------------
// Kernel C: bilinear x2 upsample from fp16 y, smem-tiled, fp32 out.
// ---------------------------------------------------------------------------
__global__ __launch_bounds__(256) void upsample_kernel(float* __restrict__ out)
{
    __shared__ float ssm[64 * 68];
    unsigned c = blockIdx.x & 511u;
    unsigned b = blockIdx.x >> 9;
    int tid = threadIdx.x;
    int wid = tid >> 5, lane = tid & 31;

    const uint4* src = (const uint4*)(g_yh + ((size_t)b * COUT + c) * HW);
#pragma unroll
    for (int j = 0; j < 2; j++) {
        int idx = tid + j * 256;
        int row = idx >> 3, col8 = idx & 7;
        uint4 v = __ldg(src + idx);
        float* dst = ssm + row * 68 + col8 * 8;
        float2 f0 = __half22float2(*(__half2*)&v.x);
        float2 f1 = __half22float2(*(__half2*)&v.y);
        float2 f2 = __half22float2(*(__half2*)&v.z);
        float2 f3 = __half22float2(*(__half2*)&v.w);
        dst[0] = f0.x; dst[1] = f0.y; dst[2] = f1.x; dst[3] = f1.y;
        dst[4] = f2.x; dst[5] = f2.y; dst[6] = f3.x; dst[7] = f3.y;
    }
    __syncthreads();

    float* outp = out + ((size_t)b * COUT + c) * OH * OW;
#pragma unroll
    for (int i = 0; i < 16; i++) {
        int oy = i * 8 + wid;
        float fy  = oy * 0.5f - 0.25f;
        float y0f = floorf(fy);
        float wy  = fy - y0f;
        int iy0 = max(0, (int)y0f);
        int iy1 = min(63, (int)y0f + 1);
        const float* r0 = ssm + iy0 * 68;
        const float* r1 = ssm + iy1 * 68;
        float* orow = outp + (size_t)oy * OW;
#pragma unroll
        for (int seg = 0; seg < 2; seg++) {
            int xc = lane + seg * 32;
            int xm = max(0, xc - 1);
            int xp = min(63, xc + 1);
            float vm = r0[xm] + wy * (r1[xm] - r0[xm]);
            float vc = r0[xc] + wy * (r1[xc] - r0[xc]);
            float vp = r0[xp] + wy * (r1[xp] - r0[xp]);
            *(float2*)(orow + 2 * xc) =
                make_float2(0.25f * vm + 0.75f * vc, 0.75f * vc + 0.25f * vp);
        }
    }
}

// ---------------------------------------------------------------------------
extern "C" void kernel_launch(void* const* d_in, const int* in_sizes, int n_in,
                              void* d_out, int out_size)
{
    const float* x      = (const float*)d_in[0];
    const float* style  = (const float*)d_in[1];
    const float* conv_w = (const float*)d_in[2];
    const float* mod_w  = (const float*)d_in[3];
    const float* mod_b  = (const float*)d_in[4];
    float* out = (float*)d_out;

    cudaFuncSetAttribute(gemm_mma, cudaFuncAttributeMaxDynamicSharedMemorySize, SM_GEMM_BYTES);

    dim3 mgrid(8, 16);
    mod_demod_kernel<<<mgrid, 256>>>(style, conv_w, mod_w, mod_b);

    dim3 fgrid(16, 4, 16);
    wfrag_kernel<<<fgrid, 256>>>(conv_w);

    dim3 xgrid(8, 16, 16);
    xcvt_kernel<<<xgrid, 256>>>(x);

    dim3 ggrid(HW / 128, COUT / 128, B_);   // (32, 4, 16)
    gemm_mma<<<ggrid, 256, SM_GEMM_BYTES>>>();

    upsample_kernel<<<B_ * COUT, 256>>>(out);
}

// round 13
// speedup vs baseline: 1.0573x; 1.0101x over previous
#include <cuda_runtime.h>
#include <cuda_fp16.h>
#include <cstdint>
#include <math.h>

// Problem dims
#define B_    16
#define CIN   512
#define COUT  512
#define H_    64
#define W_    64
#define HW    4096
#define SDIM  32
#define OH    128
#define OW    128
#define EPS   1e-8f

// Scratch
__device__ float    g_s[B_ * CIN];
__device__ float    g_demod[B_ * COUT];
__device__ uint32_t g_wh[(size_t)B_ * COUT * CIN / 2];   // fp16 A-fragment-ordered weights (8 MB)
__device__ uint4    g_xf[(size_t)B_ * 16 * 512 * 32];    // fp16 B-fragment-ordered x (67 MB)
__device__ __half   g_yh[(size_t)B_ * COUT * HW];        // conv output, fp16 (67 MB)

// ---------------------------------------------------------------------------
// Kernel A1: s[b,cin], demod[b,cout]. grid (8, 16), 256 threads.
// ---------------------------------------------------------------------------
__global__ __launch_bounds__(256) void mod_demod_kernel(
    const float* __restrict__ style,
    const float* __restrict__ conv_w,
    const float* __restrict__ mod_w,
    const float* __restrict__ mod_b)
{
    int og = blockIdx.x;
    int b  = blockIdx.y;
    int tid = threadIdx.x;
    __shared__ float s_sh[CIN];

    const float* st = style + b * SDIM;
#pragma unroll
    for (int rep = 0; rep < 2; rep++) {
        int i = tid + rep * 256;
        float acc = mod_b[i];
        const float* mw = mod_w + i * SDIM;
#pragma unroll
        for (int k = 0; k < SDIM; k++) acc += st[k] * mw[k];
        s_sh[i] = acc;
        if (og == 0) g_s[b * CIN + i] = acc;
    }
    __syncthreads();

    int wid = tid >> 5, lane = tid & 31;
#pragma unroll
    for (int cc = 0; cc < 8; cc++) {
        int o = og * 64 + wid * 8 + cc;
        const float* cw = conv_w + (size_t)o * CIN;
        float sum = 0.f;
#pragma unroll
        for (int it = 0; it < 4; it++) {
            int k4 = lane + it * 32;
            float4 v = __ldg((const float4*)cw + k4);
            int k = k4 * 4;
            float t0 = v.x * s_sh[k], t1 = v.y * s_sh[k + 1];
            float t2 = v.z * s_sh[k + 2], t3 = v.w * s_sh[k + 3];
            sum += t0 * t0 + t1 * t1 + t2 * t2 + t3 * t3;
        }
#pragma unroll
        for (int off = 16; off; off >>= 1)
            sum += __shfl_xor_sync(0xFFFFFFFFu, sum, off);
        if (lane == 0) g_demod[b * COUT + o] = rsqrtf(sum + EPS);
    }
}

// ---------------------------------------------------------------------------
// Kernel A2: fp16 weights in m16n8k16 A-fragment order.
// ---------------------------------------------------------------------------
__global__ __launch_bounds__(256) void wfrag_kernel(
    const float* __restrict__ conv_w)
{
    int c  = blockIdx.x;
    int ot = blockIdx.y;
    int b  = blockIdx.z;
    int tid = threadIdx.x;
    int lane = tid & 31, fg = tid >> 5;
    int gid = lane >> 2, tg = lane & 3;

    uint32_t* cb = g_wh + ((size_t)((b * 4 + ot) * 16 + c)) * 2048;

#pragma unroll
    for (int rep = 0; rep < 2; rep++) {
        int fgrp = fg + rep * 8;
        int g  = fgrp >> 3;
        int s  = (fgrp >> 2) & 1;
        int mt = fgrp & 3;
        int o0 = ot * 128 + g * 64 + mt * 16 + gid;
        int o1 = o0 + 8;
        int k0 = c * 32 + s * 16 + tg * 2;

        float d0 = __ldg(g_demod + b * COUT + o0);
        float d1 = __ldg(g_demod + b * COUT + o1);
        float s00 = __ldg(g_s + b * CIN + k0);
        float s01 = __ldg(g_s + b * CIN + k0 + 1);
        float s08 = __ldg(g_s + b * CIN + k0 + 8);
        float s09 = __ldg(g_s + b * CIN + k0 + 9);

        float2 w0a = __ldg((const float2*)(conv_w + (size_t)o0 * CIN + k0));
        float2 w0b = __ldg((const float2*)(conv_w + (size_t)o0 * CIN + k0 + 8));
        float2 w1a = __ldg((const float2*)(conv_w + (size_t)o1 * CIN + k0));
        float2 w1b = __ldg((const float2*)(conv_w + (size_t)o1 * CIN + k0 + 8));

        __half2 h0 = __floats2half2_rn(w0a.x * s00 * d0, w0a.y * s01 * d0);
        __half2 h1 = __floats2half2_rn(w1a.x * s00 * d1, w1a.y * s01 * d1);
        __half2 h2 = __floats2half2_rn(w0b.x * s08 * d0, w0b.y * s09 * d0);
        __half2 h3 = __floats2half2_rn(w1b.x * s08 * d1, w1b.y * s09 * d1);

        uint4 u;
        u.x = *(uint32_t*)&h0; u.y = *(uint32_t*)&h1;
        u.z = *(uint32_t*)&h2; u.w = *(uint32_t*)&h3;
        *(uint4*)(cb + fgrp * 128 + lane * 4) = u;
    }
}

// ---------------------------------------------------------------------------
// Kernel A3: x -> B-fragment order (R10 direct version — measured fastest).
// ---------------------------------------------------------------------------
__global__ __launch_bounds__(256) void xcvt_kernel(const float* __restrict__ x)
{
    unsigned blk = blockIdx.x;
    unsigned seg = blk & 63u;
    unsigned c   = (blk >> 6) & 15u;
    unsigned b   = blk >> 10;

    unsigned t  = seg * 256u + threadIdx.x;
    unsigned tg = t & 3u;
    unsigned p  = t >> 2;

    const float* xb = x + (size_t)b * CIN * HW + p;
    unsigned rbase = c * 32 + 2 * tg;

    uint4 u;
    {
        float lo = __ldg(xb + (size_t)(rbase + 0) * HW);
        float hi = __ldg(xb + (size_t)(rbase + 1) * HW);
        __half2 h = __floats2half2_rn(lo, hi); u.x = *(uint32_t*)&h;
    }
    {
        float lo = __ldg(xb + (size_t)(rbase + 8) * HW);
        float hi = __ldg(xb + (size_t)(rbase + 9) * HW);
        __half2 h = __floats2half2_rn(lo, hi); u.y = *(uint32_t*)&h;
    }
    {
        float lo = __ldg(xb + (size_t)(rbase + 16) * HW);
        float hi = __ldg(xb + (size_t)(rbase + 17) * HW);
        __half2 h = __floats2half2_rn(lo, hi); u.z = *(uint32_t*)&h;
    }
    {
        float lo = __ldg(xb + (size_t)(rbase + 24) * HW);
        float hi = __ldg(xb + (size_t)(rbase + 25) * HW);
        __half2 h = __floats2half2_rn(lo, hi); u.w = *(uint32_t*)&h;
    }

    unsigned n8 = p >> 3;
    unsigned lane_out = (p & 7u) * 4u + tg;
    g_xf[((size_t)(b * 16 + c) * 512 + n8) * 32 + lane_out] = u;
}

// ---------------------------------------------------------------------------
// Kernel B: batched GEMM, mma.sync.m16n8k16.f16.
// 6-stage cp.async, one sync per chunk: wait 4 -> sync -> bv LDS -> issue(ch+5)
// -> compute(ch). issue(ch+5) writes buf (ch-1)%6, protected by the sync.
// ---------------------------------------------------------------------------
#define A_U32 2048
#define B_U32 2048
#define STAGE_U32 (A_U32 + B_U32)
#define NSTAGE 6
#define SM_GEMM_BYTES (NSTAGE * STAGE_U32 * 4)   // 98304

__device__ __forceinline__ uint32_t smem_u32(const void* p) {
    uint32_t a;
    asm("{ .reg .u64 t; cvta.to.shared.u64 t, %1; cvt.u32.u64 %0, t; }" : "=r"(a) : "l"(p));
    return a;
}

__global__ __launch_bounds__(256, 2) void gemm_mma(void)
{
    extern __shared__ uint32_t smu[];

    int tid = threadIdx.x;
    int wid = tid >> 5, lane = tid & 31;
    int gid = lane >> 2, tg = lane & 3;
    int b = blockIdx.z, oTile = blockIdx.y * 128, pTile = blockIdx.x * 128;
    int g = wid >> 2, wn = (wid & 3) * 32, wnb = (wid & 3) * 4;

    const uint32_t* aglob = g_wh + ((size_t)((b * 4 + blockIdx.y) * 16)) * 2048;
    const uint4*    bglob = g_xf + (size_t)b * 262144 + (size_t)(pTile >> 3) * 32;

    uint32_t sm_u = smem_u32(smu);

    auto issue = [&](int ch) {
        int buf = ch % NSTAGE;
        uint32_t stage = sm_u + buf * STAGE_U32 * 4;
        const uint32_t* as_ = aglob + ch * 2048 + tid * 8;
        uint32_t ad = stage + tid * 32;
        asm volatile("cp.async.cg.shared.global [%0], [%1], 16;" :: "r"(ad),      "l"(as_)     : "memory");
        asm volatile("cp.async.cg.shared.global [%0], [%1], 16;" :: "r"(ad + 16), "l"(as_ + 4) : "memory");
        const uint4* bs_ = bglob + (size_t)ch * 16384 + tid * 2;
        uint32_t bd = stage + A_U32 * 4 + tid * 32;
        asm volatile("cp.async.cg.shared.global [%0], [%1], 16;" :: "r"(bd),      "l"(bs_)     : "memory");
        asm volatile("cp.async.cg.shared.global [%0], [%1], 16;" :: "r"(bd + 16), "l"(bs_ + 1) : "memory");
        asm volatile("cp.async.commit_group;" ::: "memory");
    };

    float c[4][4][4];
#pragma unroll
    for (int mt = 0; mt < 4; mt++)
#pragma unroll
        for (int nt = 0; nt < 4; nt++)
#pragma unroll
            for (int q = 0; q < 4; q++) c[mt][nt][q] = 0.f;

    issue(0); issue(1); issue(2); issue(3); issue(4);

    const int NCH = CIN / 32;   // 16
    for (int ch = 0; ch < NCH; ch++) {
        // Issued through min(ch+4, NCH-1); ensure chunk ch has landed.
        if (ch + 4 < NCH) {
            asm volatile("cp.async.wait_group 4;" ::: "memory");
        } else if (ch + 3 < NCH) {
            asm volatile("cp.async.wait_group 3;" ::: "memory");
        } else if (ch + 2 < NCH) {
            asm volatile("cp.async.wait_group 2;" ::: "memory");
        } else if (ch + 1 < NCH) {
            asm volatile("cp.async.wait_group 1;" ::: "memory");
        } else {
            asm volatile("cp.async.wait_group 0;" ::: "memory");
        }
        __syncthreads();

        int buf = ch % NSTAGE;
        const uint32_t* Ab = smu + buf * STAGE_U32 + g * 1024;
        const uint4*    Bb = (const uint4*)(smu + buf * STAGE_U32 + A_U32);

        // B fragments first: LDS latency overlaps the cp.async issue below.
        uint4 bv[4];
#pragma unroll
        for (int nt = 0; nt < 4; nt++)
            bv[nt] = Bb[(wnb + nt) * 32 + lane];

        if (ch + 5 < NCH) issue(ch + 5);

#pragma unroll
        for (int s = 0; s < 2; s++) {
            uint32_t af[4][4];
#pragma unroll
            for (int mt = 0; mt < 4; mt++) {
                uint4 av = *(const uint4*)(Ab + (s * 4 + mt) * 128 + lane * 4);
                af[mt][0] = av.x; af[mt][1] = av.y; af[mt][2] = av.z; af[mt][3] = av.w;
            }
#pragma unroll
            for (int mt = 0; mt < 4; mt++)
#pragma unroll
                for (int nt = 0; nt < 4; nt++) {
                    uint32_t b0 = s ? bv[nt].z : bv[nt].x;
                    uint32_t b1 = s ? bv[nt].w : bv[nt].y;
                    asm volatile(
                        "mma.sync.aligned.m16n8k16.row.col.f32.f16.f16.f32 "
                        "{%0,%1,%2,%3}, {%4,%5,%6,%7}, {%8,%9}, {%0,%1,%2,%3};"
                        : "+f"(c[mt][nt][0]), "+f"(c[mt][nt][1]),
                          "+f"(c[mt][nt][2]), "+f"(c[mt][nt][3])
                        : "r"(af[mt][0]), "r"(af[mt][1]), "r"(af[mt][2]), "r"(af[mt][3]),
                          "r"(b0), "r"(b1));
                }
        }
    }

    // Epilogue: fp16 stores.
    __half* yb = g_yh + (size_t)b * COUT * HW;
#pragma unroll
    for (int mt = 0; mt < 4; mt++) {
        int r0 = oTile + g * 64 + mt * 16 + gid;
        int r1 = r0 + 8;
#pragma unroll
        for (int nt = 0; nt < 4; nt++) {
            int col = pTile + wn + nt * 8 + tg * 2;
            __half2 h0 = __floats2half2_rn(c[mt][nt][0], c[mt][nt][1]);
            __half2 h1 = __floats2half2_rn(c[mt][nt][2], c[mt][nt][3]);
            *(__half2*)(yb + (size_t)r0 * HW + col) = h0;
            *(__half2*)(yb + (size_t)r1 * HW + col) = h1;
        }
    }
}

// ---------------------------------------------------------------------------
// Kernel C: bilinear x2 upsample from fp16 y, smem-tiled, fp32 out.
// ---------------------------------------------------------------------------
__global__ __launch_bounds__(256) void upsample_kernel(float* __restrict__ out)
{
    __shared__ float ssm[64 * 68];
    unsigned c = blockIdx.x & 511u;
    unsigned b = blockIdx.x >> 9;
    int tid = threadIdx.x;
    int wid = tid >> 5, lane = tid & 31;

    const uint4* src = (const uint4*)(g_yh + ((size_t)b * COUT + c) * HW);
#pragma unroll
    for (int j = 0; j < 2; j++) {
        int idx = tid + j * 256;
        int row = idx >> 3, col8 = idx & 7;
        uint4 v = __ldg(src + idx);
        float* dst = ssm + row * 68 + col8 * 8;
        float2 f0 = __half22float2(*(__half2*)&v.x);
        float2 f1 = __half22float2(*(__half2*)&v.y);
        float2 f2 = __half22float2(*(__half2*)&v.z);
        float2 f3 = __half22float2(*(__half2*)&v.w);
        dst[0] = f0.x; dst[1] = f0.y; dst[2] = f1.x; dst[3] = f1.y;
        dst[4] = f2.x; dst[5] = f2.y; dst[6] = f3.x; dst[7] = f3.y;
    }
    __syncthreads();

    float* outp = out + ((size_t)b * COUT + c) * OH * OW;
#pragma unroll
    for (int i = 0; i < 16; i++) {
        int oy = i * 8 + wid;
        float fy  = oy * 0.5f - 0.25f;
        float y0f = floorf(fy);
        float wy  = fy - y0f;
        int iy0 = max(0, (int)y0f);
        int iy1 = min(63, (int)y0f + 1);
        const float* r0 = ssm + iy0 * 68;
        const float* r1 = ssm + iy1 * 68;
        float* orow = outp + (size_t)oy * OW;
#pragma unroll
        for (int seg = 0; seg < 2; seg++) {
            int xc = lane + seg * 32;
            int xm = max(0, xc - 1);
            int xp = min(63, xc + 1);
            float vm = r0[xm] + wy * (r1[xm] - r0[xm]);
            float vc = r0[xc] + wy * (r1[xc] - r0[xc]);
            float vp = r0[xp] + wy * (r1[xp] - r0[xp]);
            *(float2*)(orow + 2 * xc) =
                make_float2(0.25f * vm + 0.75f * vc, 0.75f * vc + 0.25f * vp);
        }
    }
}

// ---------------------------------------------------------------------------
extern "C" void kernel_launch(void* const* d_in, const int* in_sizes, int n_in,
                              void* d_out, int out_size)
{
    const float* x      = (const float*)d_in[0];
    const float* style  = (const float*)d_in[1];
    const float* conv_w = (const float*)d_in[2];
    const float* mod_w  = (const float*)d_in[3];
    const float* mod_b  = (const float*)d_in[4];
    float* out = (float*)d_out;

    cudaFuncSetAttribute(gemm_mma, cudaFuncAttributeMaxDynamicSharedMemorySize, SM_GEMM_BYTES);

    dim3 mgrid(8, 16);
    mod_demod_kernel<<<mgrid, 256>>>(style, conv_w, mod_w, mod_b);

    dim3 fgrid(16, 4, 16);
    wfrag_kernel<<<fgrid, 256>>>(conv_w);

    xcvt_kernel<<<16384, 256>>>(x);

    dim3 ggrid(HW / 128, COUT / 128, B_);   // (32, 4, 16)
    gemm_mma<<<ggrid, 256, SM_GEMM_BYTES>>>();

    upsample_kernel<<<B_ * COUT, 256>>>(out);
}

// round 14
// speedup vs baseline: 1.0899x; 1.0308x over previous
#include <cuda_runtime.h>
#include <cuda_fp16.h>
#include <cstdint>
#include <math.h>

// Problem dims
#define B_    16
#define CIN   512
#define COUT  512
#define H_    64
#define W_    64
#define HW    4096
#define SDIM  32
#define OH    128
#define OW    128
#define EPS   1e-8f

// Scratch
__device__ uint32_t g_wh[(size_t)B_ * COUT * CIN / 2];   // fp16 A-fragment-ordered weights (8 MB)
__device__ uint4    g_xf[(size_t)B_ * 16 * 512 * 32];    // fp16 B-fragment-ordered x (67 MB)
__device__ __half   g_yh[(size_t)B_ * COUT * HW];        // conv output, fp16 (67 MB)

// ---------------------------------------------------------------------------
// Kernel A: fused style modulation + demod + fragment-ordered weight write.
// grid (4 ot, 2 gh, 16 b), 256 threads.
// Block covers couts o = ot*128 + gh*64 + [0,64); writes fgrps gh*8..gh*8+7
// for all 16 k-chunks of tile (b, ot).
// ---------------------------------------------------------------------------
__global__ __launch_bounds__(256) void wprep_kernel(
    const float* __restrict__ style,
    const float* __restrict__ conv_w,
    const float* __restrict__ mod_w,
    const float* __restrict__ mod_b)
{
    int ot = blockIdx.x;      // 0..3
    int gh = blockIdx.y;      // 0..1
    int b  = blockIdx.z;      // 0..15
    int tid = threadIdx.x;
    int wid = tid >> 5, lane = tid & 31;
    int gid = lane >> 2, tg = lane & 3;

    __shared__ float s_sh[CIN];
    __shared__ float dm_sh[64];

    // 1) style modulation s[k]
    const float* st = style + b * SDIM;
#pragma unroll
    for (int rep = 0; rep < 2; rep++) {
        int i = tid + rep * 256;
        float acc = mod_b[i];
        const float* mw = mod_w + i * SDIM;
#pragma unroll
        for (int k = 0; k < SDIM; k++) acc += st[k] * mw[k];
        s_sh[i] = acc;
    }
    __syncthreads();

    // 2) demod for this block's 64 couts: warp w -> o-locals w*8..w*8+7
    int obase = ot * 128 + gh * 64;
#pragma unroll
    for (int cc = 0; cc < 8; cc++) {
        int ol = wid * 8 + cc;
        const float* cw = conv_w + (size_t)(obase + ol) * CIN;
        float sum = 0.f;
#pragma unroll
        for (int it = 0; it < 4; it++) {
            int k4 = lane + it * 32;
            float4 v = __ldg((const float4*)cw + k4);
            int k = k4 * 4;
            float t0 = v.x * s_sh[k], t1 = v.y * s_sh[k + 1];
            float t2 = v.z * s_sh[k + 2], t3 = v.w * s_sh[k + 3];
            sum += t0 * t0 + t1 * t1 + t2 * t2 + t3 * t3;
        }
#pragma unroll
        for (int off = 16; off; off >>= 1)
            sum += __shfl_xor_sync(0xFFFFFFFFu, sum, off);
        if (lane == 0) dm_sh[ol] = rsqrtf(sum + EPS);
    }
    __syncthreads();

    // 3) fragment writes: warp wid -> fgrp = gh*8 + wid (s = wid>>2, mt = wid&3),
    //    looping over the 16 k-chunks. conv_w rows re-read from L2.
    int s  = wid >> 2;
    int mt = wid & 3;
    int fgrp = gh * 8 + wid;
    int o0l = mt * 16 + gid;        // within gh's 64
    int o1l = o0l + 8;
    int o0 = obase + o0l, o1 = obase + o1l;
    float d0 = dm_sh[o0l];
    float d1 = dm_sh[o1l];

    uint32_t* cb0 = g_wh + ((size_t)((b * 4 + ot) * 16)) * 2048 + fgrp * 128 + lane * 4;
    const float* w0row = conv_w + (size_t)o0 * CIN;
    const float* w1row = conv_w + (size_t)o1 * CIN;

#pragma unroll 4
    for (int c = 0; c < 16; c++) {
        int k0 = c * 32 + s * 16 + tg * 2;
        float s00 = s_sh[k0],     s01 = s_sh[k0 + 1];
        float s08 = s_sh[k0 + 8], s09 = s_sh[k0 + 9];

        float2 w0a = __ldg((const float2*)(w0row + k0));
        float2 w0b = __ldg((const float2*)(w0row + k0 + 8));
        float2 w1a = __ldg((const float2*)(w1row + k0));
        float2 w1b = __ldg((const float2*)(w1row + k0 + 8));

        __half2 h0 = __floats2half2_rn(w0a.x * s00 * d0, w0a.y * s01 * d0);
        __half2 h1 = __floats2half2_rn(w1a.x * s00 * d1, w1a.y * s01 * d1);
        __half2 h2 = __floats2half2_rn(w0b.x * s08 * d0, w0b.y * s09 * d0);
        __half2 h3 = __floats2half2_rn(w1b.x * s08 * d1, w1b.y * s09 * d1);

        uint4 u;
        u.x = *(uint32_t*)&h0; u.y = *(uint32_t*)&h1;
        u.z = *(uint32_t*)&h2; u.w = *(uint32_t*)&h3;
        *(uint4*)(cb0 + (size_t)c * 2048) = u;
    }
}

// ---------------------------------------------------------------------------
// Kernel A3: x -> B-fragment order (R10 direct version — measured fastest).
// ---------------------------------------------------------------------------
__global__ __launch_bounds__(256) void xcvt_kernel(const float* __restrict__ x)
{
    unsigned blk = blockIdx.x;
    unsigned seg = blk & 63u;
    unsigned c   = (blk >> 6) & 15u;
    unsigned b   = blk >> 10;

    unsigned t  = seg * 256u + threadIdx.x;
    unsigned tg = t & 3u;
    unsigned p  = t >> 2;

    const float* xb = x + (size_t)b * CIN * HW + p;
    unsigned rbase = c * 32 + 2 * tg;

    uint4 u;
    {
        float lo = __ldg(xb + (size_t)(rbase + 0) * HW);
        float hi = __ldg(xb + (size_t)(rbase + 1) * HW);
        __half2 h = __floats2half2_rn(lo, hi); u.x = *(uint32_t*)&h;
    }
    {
        float lo = __ldg(xb + (size_t)(rbase + 8) * HW);
        float hi = __ldg(xb + (size_t)(rbase + 9) * HW);
        __half2 h = __floats2half2_rn(lo, hi); u.y = *(uint32_t*)&h;
    }
    {
        float lo = __ldg(xb + (size_t)(rbase + 16) * HW);
        float hi = __ldg(xb + (size_t)(rbase + 17) * HW);
        __half2 h = __floats2half2_rn(lo, hi); u.z = *(uint32_t*)&h;
    }
    {
        float lo = __ldg(xb + (size_t)(rbase + 24) * HW);
        float hi = __ldg(xb + (size_t)(rbase + 25) * HW);
        __half2 h = __floats2half2_rn(lo, hi); u.w = *(uint32_t*)&h;
    }

    unsigned n8 = p >> 3;
    unsigned lane_out = (p & 7u) * 4u + tg;
    g_xf[((size_t)(b * 16 + c) * 512 + n8) * 32 + lane_out] = u;
}

// ---------------------------------------------------------------------------
// Kernel B: batched GEMM, mma.sync.m16n8k16.f16.
// 5-stage cp.async (measured optimum), one sync per chunk:
//   wait 3 -> sync -> bv LDS -> issue(ch+4) -> compute(ch).
// ---------------------------------------------------------------------------
#define A_U32 2048
#define B_U32 2048
#define STAGE_U32 (A_U32 + B_U32)
#define NSTAGE 5
#define SM_GEMM_BYTES (NSTAGE * STAGE_U32 * 4)   // 81920

__device__ __forceinline__ uint32_t smem_u32(const void* p) {
    uint32_t a;
    asm("{ .reg .u64 t; cvta.to.shared.u64 t, %1; cvt.u32.u64 %0, t; }" : "=r"(a) : "l"(p));
    return a;
}

__global__ __launch_bounds__(256, 2) void gemm_mma(void)
{
    extern __shared__ uint32_t smu[];

    int tid = threadIdx.x;
    int wid = tid >> 5, lane = tid & 31;
    int gid = lane >> 2, tg = lane & 3;
    int b = blockIdx.z, oTile = blockIdx.y * 128, pTile = blockIdx.x * 128;
    int g = wid >> 2, wn = (wid & 3) * 32, wnb = (wid & 3) * 4;

    const uint32_t* aglob = g_wh + ((size_t)((b * 4 + blockIdx.y) * 16)) * 2048;
    const uint4*    bglob = g_xf + (size_t)b * 262144 + (size_t)(pTile >> 3) * 32;

    uint32_t sm_u = smem_u32(smu);

    auto issue = [&](int ch) {
        int buf = ch % NSTAGE;
        uint32_t stage = sm_u + buf * STAGE_U32 * 4;
        const uint32_t* as_ = aglob + ch * 2048 + tid * 8;
        uint32_t ad = stage + tid * 32;
        asm volatile("cp.async.cg.shared.global [%0], [%1], 16;" :: "r"(ad),      "l"(as_)     : "memory");
        asm volatile("cp.async.cg.shared.global [%0], [%1], 16;" :: "r"(ad + 16), "l"(as_ + 4) : "memory");
        const uint4* bs_ = bglob + (size_t)ch * 16384 + tid * 2;
        uint32_t bd = stage + A_U32 * 4 + tid * 32;
        asm volatile("cp.async.cg.shared.global [%0], [%1], 16;" :: "r"(bd),      "l"(bs_)     : "memory");
        asm volatile("cp.async.cg.shared.global [%0], [%1], 16;" :: "r"(bd + 16), "l"(bs_ + 1) : "memory");
        asm volatile("cp.async.commit_group;" ::: "memory");
    };

    float c[4][4][4];
#pragma unroll
    for (int mt = 0; mt < 4; mt++)
#pragma unroll
        for (int nt = 0; nt < 4; nt++)
#pragma unroll
            for (int q = 0; q < 4; q++) c[mt][nt][q] = 0.f;

    issue(0); issue(1); issue(2); issue(3);

    const int NCH = CIN / 32;   // 16
    for (int ch = 0; ch < NCH; ch++) {
        if (ch + 3 < NCH) {
            asm volatile("cp.async.wait_group 3;" ::: "memory");
        } else if (ch + 2 < NCH) {
            asm volatile("cp.async.wait_group 2;" ::: "memory");
        } else if (ch + 1 < NCH) {
            asm volatile("cp.async.wait_group 1;" ::: "memory");
        } else {
            asm volatile("cp.async.wait_group 0;" ::: "memory");
        }
        __syncthreads();

        int buf = ch % NSTAGE;
        const uint32_t* Ab = smu + buf * STAGE_U32 + g * 1024;
        const uint4*    Bb = (const uint4*)(smu + buf * STAGE_U32 + A_U32);

        // B fragments first: LDS latency overlaps the cp.async issue below.
        uint4 bv[4];
#pragma unroll
        for (int nt = 0; nt < 4; nt++)
            bv[nt] = Bb[(wnb + nt) * 32 + lane];

        if (ch + 4 < NCH) issue(ch + 4);

#pragma unroll
        for (int s = 0; s < 2; s++) {
            uint32_t af[4][4];
#pragma unroll
            for (int mt = 0; mt < 4; mt++) {
                uint4 av = *(const uint4*)(Ab + (s * 4 + mt) * 128 + lane * 4);
                af[mt][0] = av.x; af[mt][1] = av.y; af[mt][2] = av.z; af[mt][3] = av.w;
            }
#pragma unroll
            for (int mt = 0; mt < 4; mt++)
#pragma unroll
                for (int nt = 0; nt < 4; nt++) {
                    uint32_t b0 = s ? bv[nt].z : bv[nt].x;
                    uint32_t b1 = s ? bv[nt].w : bv[nt].y;
                    asm volatile(
                        "mma.sync.aligned.m16n8k16.row.col.f32.f16.f16.f32 "
                        "{%0,%1,%2,%3}, {%4,%5,%6,%7}, {%8,%9}, {%0,%1,%2,%3};"
                        : "+f"(c[mt][nt][0]), "+f"(c[mt][nt][1]),
                          "+f"(c[mt][nt][2]), "+f"(c[mt][nt][3])
                        : "r"(af[mt][0]), "r"(af[mt][1]), "r"(af[mt][2]), "r"(af[mt][3]),
                          "r"(b0), "r"(b1));
                }
        }
    }

    // Epilogue: fp16 stores.
    __half* yb = g_yh + (size_t)b * COUT * HW;
#pragma unroll
    for (int mt = 0; mt < 4; mt++) {
        int r0 = oTile + g * 64 + mt * 16 + gid;
        int r1 = r0 + 8;
#pragma unroll
        for (int nt = 0; nt < 4; nt++) {
            int col = pTile + wn + nt * 8 + tg * 2;
            __half2 h0 = __floats2half2_rn(c[mt][nt][0], c[mt][nt][1]);
            __half2 h1 = __floats2half2_rn(c[mt][nt][2], c[mt][nt][3]);
            *(__half2*)(yb + (size_t)r0 * HW + col) = h0;
            *(__half2*)(yb + (size_t)r1 * HW + col) = h1;
        }
    }
}

// ---------------------------------------------------------------------------
// Kernel C: bilinear x2 upsample from fp16 y, smem-tiled, fp32 out.
// ---------------------------------------------------------------------------
__global__ __launch_bounds__(256) void upsample_kernel(float* __restrict__ out)
{
    __shared__ float ssm[64 * 68];
    unsigned c = blockIdx.x & 511u;
    unsigned b = blockIdx.x >> 9;
    int tid = threadIdx.x;
    int wid = tid >> 5, lane = tid & 31;

    const uint4* src = (const uint4*)(g_yh + ((size_t)b * COUT + c) * HW);
#pragma unroll
    for (int j = 0; j < 2; j++) {
        int idx = tid + j * 256;
        int row = idx >> 3, col8 = idx & 7;
        uint4 v = __ldg(src + idx);
        float* dst = ssm + row * 68 + col8 * 8;
        float2 f0 = __half22float2(*(__half2*)&v.x);
        float2 f1 = __half22float2(*(__half2*)&v.y);
        float2 f2 = __half22float2(*(__half2*)&v.z);
        float2 f3 = __half22float2(*(__half2*)&v.w);
        dst[0] = f0.x; dst[1] = f0.y; dst[2] = f1.x; dst[3] = f1.y;
        dst[4] = f2.x; dst[5] = f2.y; dst[6] = f3.x; dst[7] = f3.y;
    }
    __syncthreads();

    float* outp = out + ((size_t)b * COUT + c) * OH * OW;
#pragma unroll
    for (int i = 0; i < 16; i++) {
        int oy = i * 8 + wid;
        float fy  = oy * 0.5f - 0.25f;
        float y0f = floorf(fy);
        float wy  = fy - y0f;
        int iy0 = max(0, (int)y0f);
        int iy1 = min(63, (int)y0f + 1);
        const float* r0 = ssm + iy0 * 68;
        const float* r1 = ssm + iy1 * 68;
        float* orow = outp + (size_t)oy * OW;
#pragma unroll
        for (int seg = 0; seg < 2; seg++) {
            int xc = lane + seg * 32;
            int xm = max(0, xc - 1);
            int xp = min(63, xc + 1);
            float vm = r0[xm] + wy * (r1[xm] - r0[xm]);
            float vc = r0[xc] + wy * (r1[xc] - r0[xc]);
            float vp = r0[xp] + wy * (r1[xp] - r0[xp]);
            *(float2*)(orow + 2 * xc) =
                make_float2(0.25f * vm + 0.75f * vc, 0.75f * vc + 0.25f * vp);
        }
    }
}

// ---------------------------------------------------------------------------
extern "C" void kernel_launch(void* const* d_in, const int* in_sizes, int n_in,
                              void* d_out, int out_size)
{
    const float* x      = (const float*)d_in[0];
    const float* style  = (const float*)d_in[1];
    const float* conv_w = (const float*)d_in[2];
    const float* mod_w  = (const float*)d_in[3];
    const float* mod_b  = (const float*)d_in[4];
    float* out = (float*)d_out;

    cudaFuncSetAttribute(gemm_mma, cudaFuncAttributeMaxDynamicSharedMemorySize, SM_GEMM_BYTES);

    dim3 wgrid(4, 2, 16);
    wprep_kernel<<<wgrid, 256>>>(style, conv_w, mod_w, mod_b);

    xcvt_kernel<<<16384, 256>>>(x);

    dim3 ggrid(HW / 128, COUT / 128, B_);   // (32, 4, 16)
    gemm_mma<<<ggrid, 256, SM_GEMM_BYTES>>>();

    upsample_kernel<<<B_ * COUT, 256>>>(out);
}